// round 17
// baseline (speedup 1.0000x reference)
#include <cuda_runtime.h>
#include <math.h>

// Cox partial likelihood, 2 kernels (v16):
//   K1 (64 CTAs x 256): merge-rank sort per chunk of 256 — warp-bitonic
//     register sort of packed (key(T)<<32|idx), rank = lane + lower_bound
//     [0,32] in 7 other runs (ILP=7); scatter key/idx; suffix-scan e.
//     No sentinel in g_sfx (flat [NCH][CH]). Zeros out.
//   K2 (128 CTAs x 512): stage ALL keys (64KB) + ALL sfx (64KB) in SMEM;
//     4 threads per slot, each searches 16 chunks (4 ILP-4 groups, all-SMEM);
//     quarters combined in SMEM; loss for CTA's 128 slots; one atomicAdd.

#define NN   16384
#define CH   256
#define NCH  64                  // NN / CH
#define K2B  512                 // K2 block
#define K2T  128                 // slots per K2 CTA
#define K2G  (NN / K2T)          // 128 CTAs
#define QCH  (NCH / 4)           // 16 chunks per thread-quarter

typedef unsigned long long ull;

__device__ unsigned g_u  [NN];               // sorted keys, chunk-major
__device__ float    g_sfx[NN];               // suffix sums, flat [NCH][CH]
__device__ int      g_idx[NN];               // original index per sorted slot

__device__ __forceinline__ unsigned key_of(float t) {
    unsigned b = __float_as_uint(t);
    return b ^ ((unsigned)((int)b >> 31) | 0x80000000u);   // never 0 for finite t
}

__global__ void __launch_bounds__(CH)
sort_kernel(const float* __restrict__ theta, const float* __restrict__ T,
            int n, float* __restrict__ out) {
    __shared__ ull   skv[CH];
    __shared__ float se [CH];
    __shared__ float swarp[CH / 32];
    __shared__ float soff [CH / 32];

    const int c    = blockIdx.x;
    const int t    = threadIdx.x;
    const int lane = t & 31;
    const int w    = t >> 5;
    const int j    = c * CH + t;

    ull kv = (j < n) ? (((ull)key_of(T[j]) << 32) | (unsigned)j) : (ull)t;

    // warp-bitonic sort ascending (15 shuffle substages, no barriers)
#pragma unroll
    for (int k = 2; k <= 32; k <<= 1) {
#pragma unroll
        for (int s = k >> 1; s > 0; s >>= 1) {
            const bool keep_min = (((lane & s) == 0) == ((lane & k) == 0));
            const ull pkv = __shfl_xor_sync(0xFFFFFFFFu, kv, s);
            const bool take = keep_min ? (pkv < kv) : (pkv > kv);
            if (take) kv = pkv;
        }
    }

    skv[w * 32 + lane] = kv;
    __syncthreads();

    // rank = lane + lower_bound (full range [0,32]) in each other run (ILP=7)
    int rank = lane;
#pragma unroll
    for (int r = 1; r < 8; r++) {
        const ull* __restrict__ A = skv + (((w + r) & 7) << 5);
        int lo = 0;
#pragma unroll
        for (int s = 16; s > 0; s >>= 1)
            if (A[lo + s - 1] < kv) lo += s;
        if (A[lo] < kv) lo++;                 // extend to count==32
        rank += lo;
    }

    const int   idx = (int)(unsigned)kv;
    const float e   = (idx < n) ? expf(theta[idx]) : 0.0f;
    g_u  [c * CH + rank] = (unsigned)(kv >> 32);
    g_idx[c * CH + rank] = idx;
    se[rank] = e;
    __syncthreads();

    // inclusive suffix sum of se
    float ssum = se[t];
#pragma unroll
    for (int off = 1; off < 32; off <<= 1) {
        float v = __shfl_down_sync(0xFFFFFFFFu, ssum, off);
        if (lane + off < 32) ssum += v;
    }
    if (lane == 0) swarp[w] = ssum;
    __syncthreads();
    if (t < CH / 32) {                        // 8 warp totals -> exclusive suffix
        float v = swarp[t];
#pragma unroll
        for (int off = 1; off < CH / 32; off <<= 1) {
            float x = __shfl_down_sync(0xFFu, v, off);
            if (t + off < CH / 32) v += x;
        }
        soff[t] = v - swarp[t];
    }
    __syncthreads();

    g_sfx[c * CH + t] = ssum + soff[w];
    if (t == 0 && c == 0) out[0] = 0.0f;      // stream-ordered before K2
}

extern "C" __global__ void __launch_bounds__(K2B)
rank_loss_kernel(const float* __restrict__ theta, const float* __restrict__ ev,
                 int n, float* __restrict__ out) {
    extern __shared__ unsigned dyn[];
    unsigned* sk = dyn;                       // keys: 16384 u32 (64KB)
    float*    ss = (float*)(dyn + NN);        // sfx:  16384 f32 (64KB)

    __shared__ float pacc[4][K2T];
    __shared__ float wsum[4];

    const int b = blockIdx.x;
    const int t = threadIdx.x;

    // stage everything (uint4, 8 iters each, independent LDGs)
    {
        const uint4* srck = (const uint4*)g_u;
        const uint4* srcs = (const uint4*)g_sfx;
        uint4* dk = (uint4*)sk;
        uint4* ds = (uint4*)ss;
#pragma unroll
        for (int i = t; i < NN / 4; i += K2B) { dk[i] = srck[i]; ds[i] = srcs[i]; }
    }
    __syncthreads();

    const int q    = t >> 7;                  // quarter 0..3
    const int sl   = t & (K2T - 1);           // slot within tile
    const int slot = b * K2T + sl;
    const unsigned u = sk[slot];

    float acc = 0.0f;
#pragma unroll 1
    for (int g = 0; g < QCH; g += 4) {        // 4 groups of 4 ILP chains
        const int c0 = q * QCH + g;
        const unsigned* A0 = sk + (c0 + 0) * CH;
        const unsigned* A1 = sk + (c0 + 1) * CH;
        const unsigned* A2 = sk + (c0 + 2) * CH;
        const unsigned* A3 = sk + (c0 + 3) * CH;
        int l0 = 0, l1 = 0, l2 = 0, l3 = 0;
#pragma unroll
        for (int s = CH / 2; s > 0; s >>= 1) {
            if (A0[l0 + s - 1] < u) l0 += s;
            if (A1[l1 + s - 1] < u) l1 += s;
            if (A2[l2 + s - 1] < u) l2 += s;
            if (A3[l3 + s - 1] < u) l3 += s;
        }
        if (A0[l0] < u) l0++;                 // extend to [0,256]
        if (A1[l1] < u) l1++;
        if (A2[l2] < u) l2++;
        if (A3[l3] < u) l3++;
        if (l0 < CH) acc += ss[(c0 + 0) * CH + l0];   // lo==CH -> empty suffix
        if (l1 < CH) acc += ss[(c0 + 1) * CH + l1];
        if (l2 < CH) acc += ss[(c0 + 2) * CH + l2];
        if (l3 < CH) acc += ss[(c0 + 3) * CH + l3];
    }
    pacc[q][sl] = acc;
    __syncthreads();

    // threads 0..127: combine quarters, loss terms, reduce
    float term = 0.0f;
    if (t < K2T) {
        const float rss = pacc[0][t] + pacc[1][t] + pacc[2][t] + pacc[3][t];
        const int   io  = g_idx[b * K2T + t];
        term = (theta[io] - logf(rss)) * ev[io];
    }
    for (int off = 16; off > 0; off >>= 1)
        term += __shfl_down_sync(0xFFFFFFFFu, term, off);
    const int lane = t & 31, w = t >> 5;
    if (lane == 0 && w < 4) wsum[w] = term;
    __syncthreads();
    if (t == 0) {
        const float s = wsum[0] + wsum[1] + wsum[2] + wsum[3];
        atomicAdd(out, -s / (float)n);
    }
}

extern "C" void kernel_launch(void* const* d_in, const int* in_sizes, int n_in,
                              void* d_out, int out_size) {
    const float* theta = (const float*)d_in[0];
    const float* T     = (const float*)d_in[1];
    const float* ev    = (const float*)d_in[2];
    float*       out   = (float*)d_out;
    const int n = in_sizes[0];

    static int smem_set = 0;
    const int smem_bytes = 2 * NN * (int)sizeof(unsigned);  // 128KB
    if (!smem_set) {
        cudaFuncSetAttribute(rank_loss_kernel,
                             cudaFuncAttributeMaxDynamicSharedMemorySize,
                             smem_bytes);
        smem_set = 1;
    }

    sort_kernel<<<NCH, CH>>>(theta, T, n, out);
    rank_loss_kernel<<<K2G, K2B, smem_bytes>>>(theta, ev, n, out);
}